// round 14
// baseline (speedup 1.0000x reference)
#include <cuda_runtime.h>
#include <cstdint>
#include <cstddef>

#define BB 32
#define TT 128
#define LL 64
#define HH 512
#define AA 256
#define DD 512
#define NCOL 2048
#define NBLK 144
#define NTH 512

typedef unsigned long long u64;

// ---------------- device scratch ----------------
__device__ float g_xg[(size_t)TT * BB * NCOL];     // [t*32+b][col]
__device__ float g_ctr[(size_t)BB * LL * AA];      // ctx_trans [b*64+l][a]
__device__ float g_ctxC[(size_t)BB * LL * NCOL];   // context@C [b*64+l][col]
__device__ float g_attv[(size_t)BB * AA];          // [b][a]
__device__ float g_e[(size_t)LL * BB];             // raw exp scores [l*32+b]
__device__ float g_hpA[(size_t)256 * BB * 2];      // h pair buffers [k2][b]{e,o}
__device__ float g_hpB[(size_t)256 * BB * 2];
__device__ float g_zbias[512];
// contiguous flags: low poll traffic (4 lines instead of 128)
__device__ unsigned g_fatt[16];
__device__ unsigned g_fe[128];
__device__ unsigned g_fh[128];
__device__ unsigned g_epoch;

// ---------------- helpers ----------------
__device__ __forceinline__ u64 pk2(float lo, float hi) {
    u64 r; asm("mov.b64 %0, {%1,%2};" : "=l"(r) : "f"(lo), "f"(hi)); return r;
}
__device__ __forceinline__ float2 upk2(u64 v) {
    float2 r; asm("mov.b64 {%0,%1}, %2;" : "=f"(r.x), "=f"(r.y) : "l"(v)); return r;
}
__device__ __forceinline__ u64 fma2(u64 a, u64 b, u64 c) {
    u64 d; asm("fma.rn.f32x2 %0, %1, %2, %3;" : "=l"(d) : "l"(a), "l"(b), "l"(c)); return d;
}
__device__ __forceinline__ float tanh_ap(float x) {
    float y; asm("tanh.approx.f32 %0, %1;" : "=f"(y) : "f"(x)); return y;
}
__device__ __forceinline__ float sig_ap(float x) {
    return fmaf(tanh_ap(0.5f * x), 0.5f, 0.5f);
}
__device__ __forceinline__ void st_release(unsigned* p, unsigned v) {
    asm volatile("st.release.gpu.global.u32 [%0], %1;" :: "l"(p), "r"(v) : "memory");
}
__device__ __forceinline__ unsigned ld_acquire(const unsigned* p) {
    unsigned v;
    asm volatile("ld.acquire.gpu.global.u32 %0, [%1];" : "=r"(v) : "l"(p) : "memory");
    return v;
}
// vectorized relaxed poll of 4 contiguous flags; caller issues acq fence after
__device__ __forceinline__ void poll_quad(const unsigned* base, int q, unsigned gen) {
    const uint4* p = (const uint4*)base + q;
    while (true) {
        uint4 v;
        asm volatile("ld.volatile.global.v4.u32 {%0,%1,%2,%3}, [%4];"
                     : "=r"(v.x), "=r"(v.y), "=r"(v.z), "=r"(v.w) : "l"(p));
        if (v.x >= gen && v.y >= gen && v.z >= gen && v.w >= gen) break;
    }
    asm volatile("fence.acq_rel.gpu;" ::: "memory");
}

// ---------------- prologue GEMM: double-buffered, f32x2 inner product ----------------
__global__ void __launch_bounds__(256) gemm_proj(
    const float* __restrict__ A,
    const float* __restrict__ Wa, const float* __restrict__ Wb,
    const float* __restrict__ Wc, const float* __restrict__ Wd,
    const float* __restrict__ ba, const float* __restrict__ bbi,
    const float* __restrict__ bc, const float* __restrict__ bd,
    float* __restrict__ Out, int Ncols, int wN, int wstride, int tb_mode)
{
    __shared__ u64 As2[2][8][64];
    __shared__ u64 Bs2[2][8][64];
    int tid = threadIdx.x;
    int ntile = blockIdx.x, mtile = blockIdx.y;

    int gate = (ntile * 64) / 512;
    const float* Wsel = (gate == 0) ? Wa : (gate == 1) ? Wb : (gate == 2) ? Wc : Wd;
    const float* bsel = (gate == 0) ? ba : (gate == 1) ? bbi : (gate == 2) ? bc : bd;
    int ncolbase = (ntile * 64) % wN;

    int a_r = tid >> 2;
    int a_k = (tid & 3) * 4;
    int grow = mtile * 64 + a_r;
    const float* aptr;
    if (tb_mode) {
        int t = grow >> 5, b = grow & 31;
        aptr = A + ((size_t)(b * TT + t)) * DD;
    } else {
        aptr = A + (size_t)grow * DD;
    }
    int bl_k2 = (tid >> 4) & 7;
    int bl_n  = (tid & 15) * 4;
    bool bldr = tid < 128;

    int tx = tid & 15, ty = tid >> 4;
    u64 acc2[4][4];
#pragma unroll
    for (int i = 0; i < 4; i++)
#pragma unroll
        for (int j = 0; j < 4; j++) acc2[i][j] = 0;

    // preload k-chunk 0
    float4 av = *(const float4*)(aptr + a_k);
    float4 b0, b1;
    if (bldr) {
        b0 = *(const float4*)(Wsel + (size_t)(2 * bl_k2) * wstride + ncolbase + bl_n);
        b1 = *(const float4*)(Wsel + (size_t)(2 * bl_k2 + 1) * wstride + ncolbase + bl_n);
    }
    As2[0][(a_k >> 1)][a_r]     = pk2(av.x, av.y);
    As2[0][(a_k >> 1) + 1][a_r] = pk2(av.z, av.w);
    if (bldr) {
        Bs2[0][bl_k2][bl_n + 0] = pk2(b0.x, b1.x);
        Bs2[0][bl_k2][bl_n + 1] = pk2(b0.y, b1.y);
        Bs2[0][bl_k2][bl_n + 2] = pk2(b0.z, b1.z);
        Bs2[0][bl_k2][bl_n + 3] = pk2(b0.w, b1.w);
    }
    __syncthreads();

    const int NIT = DD / 16;   // 32
    for (int it = 0; it < NIT; it++) {
        int buf = it & 1;
        float4 av_n, b0_n, b1_n;
        if (it + 1 < NIT) {
            int k0 = (it + 1) * 16;
            av_n = *(const float4*)(aptr + k0 + a_k);
            if (bldr) {
                b0_n = *(const float4*)(Wsel + (size_t)(k0 + 2 * bl_k2) * wstride + ncolbase + bl_n);
                b1_n = *(const float4*)(Wsel + (size_t)(k0 + 2 * bl_k2 + 1) * wstride + ncolbase + bl_n);
            }
        }
#pragma unroll
        for (int k2 = 0; k2 < 8; k2++) {
            ulonglong2 a01 = *(const ulonglong2*)&As2[buf][k2][ty * 4];
            ulonglong2 a23 = *(const ulonglong2*)&As2[buf][k2][ty * 4 + 2];
            ulonglong2 b01 = *(const ulonglong2*)&Bs2[buf][k2][tx * 4];
            ulonglong2 b23 = *(const ulonglong2*)&Bs2[buf][k2][tx * 4 + 2];
            u64 aa[4] = {a01.x, a01.y, a23.x, a23.y};
            u64 bb4[4] = {b01.x, b01.y, b23.x, b23.y};
#pragma unroll
            for (int i = 0; i < 4; i++)
#pragma unroll
                for (int j = 0; j < 4; j++) acc2[i][j] = fma2(aa[i], bb4[j], acc2[i][j]);
        }
        if (it + 1 < NIT) {
            int nb = (it + 1) & 1;
            __syncthreads();
            As2[nb][(a_k >> 1)][a_r]     = pk2(av_n.x, av_n.y);
            As2[nb][(a_k >> 1) + 1][a_r] = pk2(av_n.z, av_n.w);
            if (bldr) {
                Bs2[nb][bl_k2][bl_n + 0] = pk2(b0_n.x, b1_n.x);
                Bs2[nb][bl_k2][bl_n + 1] = pk2(b0_n.y, b1_n.y);
                Bs2[nb][bl_k2][bl_n + 2] = pk2(b0_n.z, b1_n.z);
                Bs2[nb][bl_k2][bl_n + 3] = pk2(b0_n.w, b1_n.w);
            }
            __syncthreads();
        }
    }
#pragma unroll
    for (int i = 0; i < 4; i++) {
        int gr = mtile * 64 + ty * 4 + i;
        float r[4];
#pragma unroll
        for (int j = 0; j < 4; j++) {
            float2 v = upk2(acc2[i][j]);
            r[j] = v.x + v.y + bsel[(ncolbase + tx * 4 + j) % wN];
        }
        *(float4*)(Out + (size_t)gr * Ncols + ntile * 64 + tx * 4) =
            make_float4(r[0], r[1], r[2], r[3]);
    }
}

// smem map (floats)
#define OFF_H    8192
#define OFF_RED  24576
#define OFF_ACC  28672
#define OFF_DOT  29184
#define OFF_E    29696
#define OFF_APR  31744
#define OFF_ATT  33792
#define OFF_A    34048
#define OFF_W2   34112
#define OFF_SUMA 34368
#define OFF_CST  34400
#define OFF_HST  34528
#define SMEM_FLOATS 34656

// ---------------- persistent recurrent kernel ----------------
__global__ void __launch_bounds__(NTH, 1) recur_kernel(
    const float* __restrict__ context,
    const float* __restrict__ mask,
    const int*   __restrict__ cmask,
    const float* __restrict__ U0, const float* __restrict__ U1,
    const float* __restrict__ U2, const float* __restrict__ U3,
    const float* __restrict__ W1h,
    const float* __restrict__ W2, const float* __restrict__ b2,
    float* __restrict__ out)
{
    extern __shared__ float smem[];
    u64*   sW64   = (u64*)smem;                    // [k2][16 cols] pairs
    float* sH     = smem + OFF_H;                  // h pairs [k2][32 b]
    u64*   sH64   = (u64*)sH;
    float* sRed   = smem + OFF_RED;                // 4096
    float* sAcc   = smem + OFF_ACC;                // 512 [ci][b]
    float* sDot   = smem + OFF_DOT;                // 512 [ci][b]
    float* sE     = smem + OFF_E;                  // 2048 [l][b]
    u64*   sApr64 = (u64*)(smem + OFF_APR);        // 1024 [l2][b]
    float* sAtt   = smem + OFF_ATT;                // 256
    float* sA     = smem + OFF_A;                  // 64
    float* sW2s   = smem + OFF_W2;                 // 256
    float* sSumA  = smem + OFF_SUMA;               // 32
    float* sCst   = smem + OFF_CST;                // 128
    float* sHst   = smem + OFF_HST;                // 128

    const int tid = threadIdx.x;
    const int bid = blockIdx.x;
    const bool isCol = (bid < 128);
    float* out_h = out;
    float* out_c = out + (size_t)BB * TT * HH;
    float* out_x = out + (size_t)2 * BB * TT * HH;
    const float b2v = b2[0];

    unsigned base = ld_acquire(&g_epoch);

    // roles
    const int ch0 = bid * 4;
    const int ab  = bid - 128;
    const int pb  = bid >> 2;
    const int pq  = bid & 3;

    // P1 thread roles: 2 cols x 4 b x 32 k2
    const int cp = tid & 7;
    const int bq = (tid >> 3) & 7;
    const int kq = tid >> 6;

    // ---- startup: weight slice into SMEM ----
    for (int i = tid; i < 4096; i += NTH) {
        int k2 = i >> 4, ci = i & 15;
        float e, o;
        if (isCol) {
            int g = ci >> 2, ch = ch0 + (ci & 3);
            const float* Ug = (g == 0) ? U0 : (g == 1) ? U1 : (g == 2) ? U2 : U3;
            e = Ug[(size_t)(2 * k2) * 512 + ch];
            o = Ug[(size_t)(2 * k2 + 1) * 512 + ch];
        } else {
            int a = ab * 16 + ci;
            e = W1h[(size_t)(2 * k2) * AA + a];
            o = W1h[(size_t)(2 * k2 + 1) * AA + a];
        }
        sW64[i] = pk2(e, o);
    }
    // ---- startup: register-resident ctxC (col only) ----
    u64 rv[32];
    {
        int ci = tid >> 5, b = tid & 31;
        if (isCol) {
            int col = (ci >> 2) * 512 + ch0 + (ci & 3);
            const float* cc = g_ctxC + (size_t)(b * 64) * NCOL + col;
#pragma unroll
            for (int li = 0; li < 32; li++) {
                float e = cc[(size_t)(2 * li) * NCOL];
                float o = cc[(size_t)(2 * li + 1) * NCOL];
                rv[li] = pk2(e, o);
            }
        } else {
#pragma unroll
            for (int li = 0; li < 32; li++) rv[li] = 0;
        }
    }
    if (tid < AA) sW2s[tid] = W2[tid];
    if (tid < 128) { sCst[tid] = 0.f; sHst[tid] = 0.f; }
    __syncthreads();

    for (int t = 0; t < TT; t++) {
        const unsigned gen = base + (unsigned)(t + 1);
        const float* hread = (t & 1) ? g_hpA : g_hpB;
        float* hwrite = (t & 1) ? g_hpB : g_hpA;

        // ===== prefetch xg early (hides L2 latency behind P1) =====
        float xgpre = 0.f;
        if (isCol) {
            int b = tid >> 4, ci = tid & 15;
            int col = (ci >> 2) * 512 + ch0 + (ci & 3);
            xgpre = __ldcg(&g_xg[((size_t)t * BB + b) * NCOL + col]);
        }

        // ===== load h broadcast (L2-direct) =====
        if (t > 0) {
            const float4* src = (const float4*)hread;
            float4* dst = (float4*)sH;
            for (int f4 = tid; f4 < 4096; f4 += NTH) dst[f4] = __ldcg(src + f4);
        }
        __syncthreads();

        // ===== P1 matvec: 2 cols x 4 b per thread =====
        u64 ac[2][4];
#pragma unroll
        for (int i = 0; i < 2; i++)
#pragma unroll
            for (int j = 0; j < 4; j++) ac[i][j] = 0;
        if (t > 0) {
            const u64* wp = sW64 + (kq * 32) * 16 + cp * 2;
            const u64* hp = sH64 + (kq * 32) * 32 + bq * 4;
#pragma unroll 8
            for (int p = 0; p < 32; p++) {
                ulonglong2 w2 = *(const ulonglong2*)wp;
                ulonglong2 ha = *(const ulonglong2*)hp;
                ulonglong2 hb = *(const ulonglong2*)(hp + 2);
                ac[0][0] = fma2(w2.x, ha.x, ac[0][0]);
                ac[0][1] = fma2(w2.x, ha.y, ac[0][1]);
                ac[0][2] = fma2(w2.x, hb.x, ac[0][2]);
                ac[0][3] = fma2(w2.x, hb.y, ac[0][3]);
                ac[1][0] = fma2(w2.y, ha.x, ac[1][0]);
                ac[1][1] = fma2(w2.y, ha.y, ac[1][1]);
                ac[1][2] = fma2(w2.y, hb.x, ac[1][2]);
                ac[1][3] = fma2(w2.y, hb.y, ac[1][3]);
                wp += 16; hp += 32;
            }
        }
#pragma unroll
        for (int bi = 0; bi < 4; bi++) {
            float2 r0 = upk2(ac[0][bi]);
            float2 r1 = upk2(ac[1][bi]);
            *(float2*)&sRed[kq * 512 + (bq * 4 + bi) * 16 + cp * 2] =
                make_float2(r0.x + r0.y, r1.x + r1.y);
        }
        __syncthreads();
        {
            float s = 0.f;
#pragma unroll
            for (int q = 0; q < 8; q++) s += sRed[q * 512 + tid];
            int b = tid >> 4, ci = tid & 15;
            if (isCol) {
                sAcc[ci * 32 + b] = s + xgpre;
            } else {
                g_attv[b * AA + ab * 16 + ci] = s;
            }
        }
        __syncthreads();

        if (!isCol) {
            // att block: publish attv, then wait out the step (packed poll)
            if (tid == 0) st_release(&g_fatt[ab], gen);
            if (tid < 32) poll_quad(g_fh, tid, gen);
            __syncthreads();
        } else {
            // ===== col: wait attv (16 flags = 4 quads), distributed scores =====
            if (tid < 4) poll_quad(g_fatt, tid, gen);
            __syncthreads();
            if (tid < AA) sAtt[tid] = __ldcg(&g_attv[pb * AA + tid]);
            __syncthreads();
            {
                int w = tid >> 5, lane = tid & 31;
                int l = pq * 16 + w;
                const float* ct = g_ctr + ((size_t)pb * LL + l) * AA;  // L1-resident
                float p = 0.f;
#pragma unroll
                for (int j = 0; j < 8; j++) {
                    int a = lane + j * 32;
                    p += tanh_ap(ct[a] + sAtt[a]) * sW2s[a];
                }
#pragma unroll
                for (int o = 16; o > 0; o >>= 1) p += __shfl_xor_sync(0xffffffffu, p, o);
                if (lane == 0)
                    g_e[l * 32 + pb] = __expf(p + b2v) * (float)cmask[pb * LL + l];
            }
            __syncthreads();
            if (tid == 0) st_release(&g_fe[bid], gen);
            if (tid < 32) poll_quad(g_fe, tid, gen);
            __syncthreads();
            // load all e [l][b]
            ((float4*)sE)[tid] = __ldcg(((const float4*)g_e) + tid);
            __syncthreads();
            if (tid < 32) {
                float s = 0.f;
#pragma unroll
                for (int i = 0; i < 64; i++) s += sE[i * 32 + tid];
                sSumA[tid] = __fdividef(1.0f, s);
            }
            __syncthreads();
            // a-pairs [l2][b] + scalar a for own batch
            {
                for (int i = tid; i < 1024; i += NTH) {
                    int l2 = i >> 5, b = i & 31;
                    float rs = sSumA[b];
                    sApr64[i] = pk2(sE[(2 * l2) * 32 + b] * rs,
                                    sE[(2 * l2 + 1) * 32 + b] * rs);
                }
                if (tid < 64) sA[tid] = sE[tid * 32 + pb] * sSumA[pb];
            }
            __syncthreads();
            // gsum from registers
            {
                int ci = tid >> 5, b = tid & 31;
                u64 acc = 0;
#pragma unroll
                for (int li = 0; li < 32; li++)
                    acc = fma2(rv[li], sApr64[li * 32 + b], acc);
                float2 r = upk2(acc);
                sDot[ci * 32 + b] = r.x + r.y;
            }
            __syncthreads();
            // ===== fused epilogue FIRST (h publication is the critical path) =====
            if (tid < 64) {
                int b = tid & 31, j = tid >> 5;
                float m = mask[b * TT + t];
                float hn2[2], cn2[2];
#pragma unroll
                for (int pp = 0; pp < 2; pp++) {
                    int chI = 2 * j + pp;
                    float gs[4];
#pragma unroll
                    for (int g = 0; g < 4; g++) {
                        int ci = g * 4 + chI;
                        gs[g] = sAcc[ci * 32 + b] + sDot[ci * 32 + b];
                    }
                    float cprev = sCst[chI * 32 + b];
                    float hprev = sHst[chI * 32 + b];
                    float iv = sig_ap(gs[0]);
                    float fv = sig_ap(gs[1]);
                    float gv = tanh_ap(gs[2]);
                    float ov = sig_ap(gs[3]);
                    float cn = fv * cprev + iv * gv;
                    float hn = ov * tanh_ap(cn);
                    hn = (1.f - m) * hprev + m * hn;
                    cn = (1.f - m) * cprev + m * cn;
                    sCst[chI * 32 + b] = cn;
                    sHst[chI * 32 + b] = hn;
                    hn2[pp] = hn; cn2[pp] = cn;
                }
                int ch = ch0 + 2 * j;
                *(u64*)&hwrite[((size_t)(ch >> 1) * 32 + b) * 2] = pk2(hn2[0], hn2[1]);
                *(float2*)(out_h + ((size_t)b * TT + t) * HH + ch) = make_float2(hn2[0], hn2[1]);
                *(float2*)(out_c + ((size_t)b * TT + t) * HH + ch) = make_float2(cn2[0], cn2[1]);
            }
            __syncthreads();
            if (tid == 0) st_release(&g_fh[bid], gen);
            // ===== out_x (off the inter-block critical path) =====
            if (tid < 256) {
                int lg = tid >> 5, d4 = tid & 31;
                float4 xp = make_float4(0.f, 0.f, 0.f, 0.f);
                const float* cb = context + ((size_t)pb * LL + lg * 8) * DD + pq * 128 + d4 * 4;
#pragma unroll
                for (int li = 0; li < 8; li++) {
                    float av = sA[lg * 8 + li];
                    float4 v = *(const float4*)(cb + (size_t)li * DD);
                    xp.x += av * v.x; xp.y += av * v.y; xp.z += av * v.z; xp.w += av * v.w;
                }
                *(float4*)&sRed[tid * 4] = xp;
            }
            __syncthreads();
            if (tid < 32) {
                float4 s = make_float4(0.f, 0.f, 0.f, 0.f);
#pragma unroll
                for (int lg = 0; lg < 8; lg++) {
                    float4 v = *(const float4*)&sRed[(lg * 32 + tid) * 4];
                    s.x += v.x; s.y += v.y; s.z += v.z; s.w += v.w;
                }
                *(float4*)(out_x + ((size_t)pb * TT + t) * DD + pq * 128 + tid * 4) = s;
            }
            // ===== end-of-step barrier on col h-flags (packed poll) =====
            if (tid < 32) poll_quad(g_fh, tid, gen);
            __syncthreads();
        }
    }

    if (bid == 0 && tid == 0)
        st_release(&g_epoch, base + (unsigned)TT);
}

// ---------------- host launcher ----------------
extern "C" void kernel_launch(void* const* d_in, const int* in_sizes, int n_in,
                              void* d_out, int out_size) {
    (void)in_sizes; (void)n_in; (void)out_size;
    const float* X    = (const float*)d_in[0];
    const float* ctx  = (const float*)d_in[1];
    const float* mask = (const float*)d_in[2];
    const int*   cm   = (const int*)d_in[3];
    const float* W[4]; const float* U[4]; const float* C[4]; const float* bi[4];
    for (int gg = 0; gg < 4; gg++) {
        W[gg]  = (const float*)d_in[4 + 4 * gg];
        U[gg]  = (const float*)d_in[5 + 4 * gg];
        C[gg]  = (const float*)d_in[6 + 4 * gg];
        bi[gg] = (const float*)d_in[7 + 4 * gg];
    }
    const float* attW1c = (const float*)d_in[20];
    const float* attB1  = (const float*)d_in[22];
    const float* attW1h = (const float*)d_in[21];
    const float* attW2  = (const float*)d_in[23];
    const float* attB2  = (const float*)d_in[24];
    float* out = (float*)d_out;

    float *xg_ptr = nullptr, *ctr_ptr = nullptr, *ctxC_ptr = nullptr, *zb_ptr = nullptr;
    cudaGetSymbolAddress((void**)&xg_ptr, g_xg);
    cudaGetSymbolAddress((void**)&ctr_ptr, g_ctr);
    cudaGetSymbolAddress((void**)&ctxC_ptr, g_ctxC);
    cudaGetSymbolAddress((void**)&zb_ptr, g_zbias);

    // xg = X@W + b : rows (t*32+b), cols 2048
    dim3 grid1(NCOL / 64, (TT * BB) / 64);
    gemm_proj<<<grid1, 256>>>(X, W[0], W[1], W[2], W[3],
                              bi[0], bi[1], bi[2], bi[3],
                              xg_ptr, NCOL, 512, 512, 1);
    // ctx_trans = context@att_ctx_W1 + b1
    dim3 grid2(AA / 64, (BB * LL) / 64);
    gemm_proj<<<grid2, 256>>>(ctx, attW1c, attW1c, attW1c, attW1c,
                              attB1, attB1, attB1, attB1,
                              ctr_ptr, AA, AA, AA, 0);
    // ctxC = context@C
    dim3 grid3(NCOL / 64, (BB * LL) / 64);
    gemm_proj<<<grid3, 256>>>(ctx, C[0], C[1], C[2], C[3],
                              zb_ptr, zb_ptr, zb_ptr, zb_ptr,
                              ctxC_ptr, NCOL, 512, 512, 0);

    size_t smem_bytes = (size_t)SMEM_FLOATS * sizeof(float);
    static bool attr_set = false;
    if (!attr_set) {
        cudaFuncSetAttribute(recur_kernel, cudaFuncAttributeMaxDynamicSharedMemorySize,
                             (int)smem_bytes);
        attr_set = true;
    }
    recur_kernel<<<NBLK, NTH, smem_bytes>>>(ctx, mask, cm,
                                            U[0], U[1], U[2], U[3], attW1h,
                                            attW2, attB2, out);
}

// round 15
// speedup vs baseline: 1.4716x; 1.4716x over previous
#include <cuda_runtime.h>
#include <cstdint>
#include <cstddef>

#define BB 32
#define TT 128
#define LL 64
#define HH 512
#define AA 256
#define DD 512
#define NCOL 2048
#define NBLK 144
#define NTH 512

typedef unsigned long long u64;

// ---------------- device scratch ----------------
__device__ float g_xg[(size_t)TT * BB * NCOL];     // [t*32+b][col]
__device__ float g_ctr[(size_t)BB * LL * AA];      // ctx_trans [b*64+l][a]
__device__ float g_ctxC[(size_t)BB * LL * NCOL];   // context@C [b*64+l][col]
__device__ float g_attv[(size_t)BB * AA];          // [b][a]
__device__ float g_e[(size_t)LL * BB];             // raw exp scores [l*32+b]
__device__ float g_hpA[(size_t)256 * BB * 2];      // h pair buffers [k2][b]{e,o}
__device__ float g_hpB[(size_t)256 * BB * 2];
__device__ float g_zbias[512];
__device__ unsigned g_fatt[16 * 32];               // padded flags (128B apart)
__device__ unsigned g_fe[128 * 32];
__device__ unsigned g_fh[128 * 32];
__device__ unsigned g_epoch;

// ---------------- helpers ----------------
__device__ __forceinline__ u64 pk2(float lo, float hi) {
    u64 r; asm("mov.b64 %0, {%1,%2};" : "=l"(r) : "f"(lo), "f"(hi)); return r;
}
__device__ __forceinline__ float2 upk2(u64 v) {
    float2 r; asm("mov.b64 {%0,%1}, %2;" : "=f"(r.x), "=f"(r.y) : "l"(v)); return r;
}
__device__ __forceinline__ u64 fma2(u64 a, u64 b, u64 c) {
    u64 d; asm("fma.rn.f32x2 %0, %1, %2, %3;" : "=l"(d) : "l"(a), "l"(b), "l"(c)); return d;
}
__device__ __forceinline__ float tanh_ap(float x) {
    float y; asm("tanh.approx.f32 %0, %1;" : "=f"(y) : "f"(x)); return y;
}
__device__ __forceinline__ float sig_ap(float x) {
    return fmaf(tanh_ap(0.5f * x), 0.5f, 0.5f);
}
__device__ __forceinline__ void st_release(unsigned* p, unsigned v) {
    asm volatile("st.release.gpu.global.u32 [%0], %1;" :: "l"(p), "r"(v) : "memory");
}
__device__ __forceinline__ unsigned ld_acquire(const unsigned* p) {
    unsigned v;
    asm volatile("ld.acquire.gpu.global.u32 %0, [%1];" : "=r"(v) : "l"(p) : "memory");
    return v;
}

// ---------------- prologue GEMM: double-buffered, f32x2 inner product ----------------
__global__ void __launch_bounds__(256) gemm_proj(
    const float* __restrict__ A,
    const float* __restrict__ Wa, const float* __restrict__ Wb,
    const float* __restrict__ Wc, const float* __restrict__ Wd,
    const float* __restrict__ ba, const float* __restrict__ bbi,
    const float* __restrict__ bc, const float* __restrict__ bd,
    float* __restrict__ Out, int Ncols, int wN, int wstride, int tb_mode)
{
    __shared__ u64 As2[2][8][64];
    __shared__ u64 Bs2[2][8][64];
    int tid = threadIdx.x;
    int ntile = blockIdx.x, mtile = blockIdx.y;

    int gate = (ntile * 64) / 512;
    const float* Wsel = (gate == 0) ? Wa : (gate == 1) ? Wb : (gate == 2) ? Wc : Wd;
    const float* bsel = (gate == 0) ? ba : (gate == 1) ? bbi : (gate == 2) ? bc : bd;
    int ncolbase = (ntile * 64) % wN;

    int a_r = tid >> 2;
    int a_k = (tid & 3) * 4;
    int grow = mtile * 64 + a_r;
    const float* aptr;
    if (tb_mode) {
        int t = grow >> 5, b = grow & 31;
        aptr = A + ((size_t)(b * TT + t)) * DD;
    } else {
        aptr = A + (size_t)grow * DD;
    }
    int bl_k2 = (tid >> 4) & 7;
    int bl_n  = (tid & 15) * 4;
    bool bldr = tid < 128;

    int tx = tid & 15, ty = tid >> 4;
    u64 acc2[4][4];
#pragma unroll
    for (int i = 0; i < 4; i++)
#pragma unroll
        for (int j = 0; j < 4; j++) acc2[i][j] = 0;

    // preload k-chunk 0
    float4 av = *(const float4*)(aptr + a_k);
    float4 b0, b1;
    if (bldr) {
        b0 = *(const float4*)(Wsel + (size_t)(2 * bl_k2) * wstride + ncolbase + bl_n);
        b1 = *(const float4*)(Wsel + (size_t)(2 * bl_k2 + 1) * wstride + ncolbase + bl_n);
    }
    As2[0][(a_k >> 1)][a_r]     = pk2(av.x, av.y);
    As2[0][(a_k >> 1) + 1][a_r] = pk2(av.z, av.w);
    if (bldr) {
        Bs2[0][bl_k2][bl_n + 0] = pk2(b0.x, b1.x);
        Bs2[0][bl_k2][bl_n + 1] = pk2(b0.y, b1.y);
        Bs2[0][bl_k2][bl_n + 2] = pk2(b0.z, b1.z);
        Bs2[0][bl_k2][bl_n + 3] = pk2(b0.w, b1.w);
    }
    __syncthreads();

    const int NIT = DD / 16;   // 32
    for (int it = 0; it < NIT; it++) {
        int buf = it & 1;
        float4 av_n, b0_n, b1_n;
        if (it + 1 < NIT) {
            int k0 = (it + 1) * 16;
            av_n = *(const float4*)(aptr + k0 + a_k);
            if (bldr) {
                b0_n = *(const float4*)(Wsel + (size_t)(k0 + 2 * bl_k2) * wstride + ncolbase + bl_n);
                b1_n = *(const float4*)(Wsel + (size_t)(k0 + 2 * bl_k2 + 1) * wstride + ncolbase + bl_n);
            }
        }
#pragma unroll
        for (int k2 = 0; k2 < 8; k2++) {
            ulonglong2 a01 = *(const ulonglong2*)&As2[buf][k2][ty * 4];
            ulonglong2 a23 = *(const ulonglong2*)&As2[buf][k2][ty * 4 + 2];
            ulonglong2 b01 = *(const ulonglong2*)&Bs2[buf][k2][tx * 4];
            ulonglong2 b23 = *(const ulonglong2*)&Bs2[buf][k2][tx * 4 + 2];
            u64 aa[4] = {a01.x, a01.y, a23.x, a23.y};
            u64 bb4[4] = {b01.x, b01.y, b23.x, b23.y};
#pragma unroll
            for (int i = 0; i < 4; i++)
#pragma unroll
                for (int j = 0; j < 4; j++) acc2[i][j] = fma2(aa[i], bb4[j], acc2[i][j]);
        }
        if (it + 1 < NIT) {
            int nb = (it + 1) & 1;
            __syncthreads();
            As2[nb][(a_k >> 1)][a_r]     = pk2(av_n.x, av_n.y);
            As2[nb][(a_k >> 1) + 1][a_r] = pk2(av_n.z, av_n.w);
            if (bldr) {
                Bs2[nb][bl_k2][bl_n + 0] = pk2(b0_n.x, b1_n.x);
                Bs2[nb][bl_k2][bl_n + 1] = pk2(b0_n.y, b1_n.y);
                Bs2[nb][bl_k2][bl_n + 2] = pk2(b0_n.z, b1_n.z);
                Bs2[nb][bl_k2][bl_n + 3] = pk2(b0_n.w, b1_n.w);
            }
            __syncthreads();
        }
    }
#pragma unroll
    for (int i = 0; i < 4; i++) {
        int gr = mtile * 64 + ty * 4 + i;
        float r[4];
#pragma unroll
        for (int j = 0; j < 4; j++) {
            float2 v = upk2(acc2[i][j]);
            r[j] = v.x + v.y + bsel[(ncolbase + tx * 4 + j) % wN];
        }
        *(float4*)(Out + (size_t)gr * Ncols + ntile * 64 + tx * 4) =
            make_float4(r[0], r[1], r[2], r[3]);
    }
}

// smem map (floats)
#define OFF_H    8192
#define OFF_RED  24576
#define OFF_ACC  28672
#define OFF_DOT  29184
#define OFF_E    29696
#define OFF_APR  31744
#define OFF_ATT  33792
#define OFF_A    34048
#define OFF_W2   34112
#define OFF_SUMA 34368
#define OFF_CST  34400
#define OFF_HST  34528
#define SMEM_FLOATS 34656

// ---------------- persistent recurrent kernel (R12 structure, unchanged) ----------------
__global__ void __launch_bounds__(NTH, 1) recur_kernel(
    const float* __restrict__ context,
    const float* __restrict__ mask,
    const int*   __restrict__ cmask,
    const float* __restrict__ U0, const float* __restrict__ U1,
    const float* __restrict__ U2, const float* __restrict__ U3,
    const float* __restrict__ W1h,
    const float* __restrict__ W2, const float* __restrict__ b2,
    float* __restrict__ out)
{
    extern __shared__ float smem[];
    u64*   sW64   = (u64*)smem;                    // [k2][16 cols] pairs
    float* sH     = smem + OFF_H;                  // h pairs [k2][32 b]
    u64*   sH64   = (u64*)sH;
    float* sRed   = smem + OFF_RED;                // 4096
    float* sAcc   = smem + OFF_ACC;                // 512 [ci][b]
    float* sDot   = smem + OFF_DOT;                // 512 [ci][b]
    float* sE     = smem + OFF_E;                  // 2048 [l][b]
    u64*   sApr64 = (u64*)(smem + OFF_APR);        // 1024 [l2][b]
    float* sAtt   = smem + OFF_ATT;                // 256
    float* sA     = smem + OFF_A;                  // 64
    float* sW2s   = smem + OFF_W2;                 // 256
    float* sSumA  = smem + OFF_SUMA;               // 32
    float* sCst   = smem + OFF_CST;                // 128
    float* sHst   = smem + OFF_HST;                // 128

    const int tid = threadIdx.x;
    const int bid = blockIdx.x;
    const bool isCol = (bid < 128);
    float* out_h = out;
    float* out_c = out + (size_t)BB * TT * HH;
    float* out_x = out + (size_t)2 * BB * TT * HH;
    const float b2v = b2[0];

    unsigned base = ld_acquire(&g_epoch);

    // roles
    const int ch0 = bid * 4;
    const int ab  = bid - 128;
    const int pb  = bid >> 2;
    const int pq  = bid & 3;

    // P1 thread roles: 2 cols x 4 b x 32 k2
    const int cp = tid & 7;
    const int bq = (tid >> 3) & 7;
    const int kq = tid >> 6;

    // ---- startup: weight slice into SMEM ----
    for (int i = tid; i < 4096; i += NTH) {
        int k2 = i >> 4, ci = i & 15;
        float e, o;
        if (isCol) {
            int g = ci >> 2, ch = ch0 + (ci & 3);
            const float* Ug = (g == 0) ? U0 : (g == 1) ? U1 : (g == 2) ? U2 : U3;
            e = Ug[(size_t)(2 * k2) * 512 + ch];
            o = Ug[(size_t)(2 * k2 + 1) * 512 + ch];
        } else {
            int a = ab * 16 + ci;
            e = W1h[(size_t)(2 * k2) * AA + a];
            o = W1h[(size_t)(2 * k2 + 1) * AA + a];
        }
        sW64[i] = pk2(e, o);
    }
    // ---- startup: register-resident ctxC (col only) ----
    u64 rv[32];
    {
        int ci = tid >> 5, b = tid & 31;
        if (isCol) {
            int col = (ci >> 2) * 512 + ch0 + (ci & 3);
            const float* cc = g_ctxC + (size_t)(b * 64) * NCOL + col;
#pragma unroll
            for (int li = 0; li < 32; li++) {
                float e = cc[(size_t)(2 * li) * NCOL];
                float o = cc[(size_t)(2 * li + 1) * NCOL];
                rv[li] = pk2(e, o);
            }
        } else {
#pragma unroll
            for (int li = 0; li < 32; li++) rv[li] = 0;
        }
    }
    if (tid < AA) sW2s[tid] = W2[tid];
    if (tid < 128) { sCst[tid] = 0.f; sHst[tid] = 0.f; }
    __syncthreads();

    for (int t = 0; t < TT; t++) {
        const unsigned gen = base + (unsigned)(t + 1);
        const float* hread = (t & 1) ? g_hpA : g_hpB;
        float* hwrite = (t & 1) ? g_hpB : g_hpA;

        // ===== prefetch xg early (hides L2 latency behind P1) =====
        float xgpre = 0.f;
        if (isCol) {
            int b = tid >> 4, ci = tid & 15;
            int col = (ci >> 2) * 512 + ch0 + (ci & 3);
            xgpre = __ldcg(&g_xg[((size_t)t * BB + b) * NCOL + col]);
        }

        // ===== load h broadcast (L2-direct) =====
        if (t > 0) {
            const float4* src = (const float4*)hread;
            float4* dst = (float4*)sH;
            for (int f4 = tid; f4 < 4096; f4 += NTH) dst[f4] = __ldcg(src + f4);
        }
        __syncthreads();

        // ===== P1 matvec: 2 cols x 4 b per thread =====
        u64 ac[2][4];
#pragma unroll
        for (int i = 0; i < 2; i++)
#pragma unroll
            for (int j = 0; j < 4; j++) ac[i][j] = 0;
        if (t > 0) {
            const u64* wp = sW64 + (kq * 32) * 16 + cp * 2;
            const u64* hp = sH64 + (kq * 32) * 32 + bq * 4;
#pragma unroll 8
            for (int p = 0; p < 32; p++) {
                ulonglong2 w2 = *(const ulonglong2*)wp;
                ulonglong2 ha = *(const ulonglong2*)hp;
                ulonglong2 hb = *(const ulonglong2*)(hp + 2);
                ac[0][0] = fma2(w2.x, ha.x, ac[0][0]);
                ac[0][1] = fma2(w2.x, ha.y, ac[0][1]);
                ac[0][2] = fma2(w2.x, hb.x, ac[0][2]);
                ac[0][3] = fma2(w2.x, hb.y, ac[0][3]);
                ac[1][0] = fma2(w2.y, ha.x, ac[1][0]);
                ac[1][1] = fma2(w2.y, ha.y, ac[1][1]);
                ac[1][2] = fma2(w2.y, hb.x, ac[1][2]);
                ac[1][3] = fma2(w2.y, hb.y, ac[1][3]);
                wp += 16; hp += 32;
            }
        }
#pragma unroll
        for (int bi = 0; bi < 4; bi++) {
            float2 r0 = upk2(ac[0][bi]);
            float2 r1 = upk2(ac[1][bi]);
            *(float2*)&sRed[kq * 512 + (bq * 4 + bi) * 16 + cp * 2] =
                make_float2(r0.x + r0.y, r1.x + r1.y);
        }
        __syncthreads();
        {
            float s = 0.f;
#pragma unroll
            for (int q = 0; q < 8; q++) s += sRed[q * 512 + tid];
            int b = tid >> 4, ci = tid & 15;
            if (isCol) {
                sAcc[ci * 32 + b] = s + xgpre;
            } else {
                g_attv[b * AA + ab * 16 + ci] = s;
            }
        }
        __syncthreads();

        if (!isCol) {
            // att block: publish attv, then wait out the step
            if (tid == 0) st_release(&g_fatt[ab * 32], gen);
            if (tid < 128) {
                while (ld_acquire(&g_fh[tid * 32]) < gen) { }
            }
            __syncthreads();
        } else {
            // ===== col: wait attv, distributed scores =====
            if (tid < 16) {
                while (ld_acquire(&g_fatt[tid * 32]) < gen) { }
            }
            __syncthreads();
            if (tid < AA) sAtt[tid] = __ldcg(&g_attv[pb * AA + tid]);
            __syncthreads();
            {
                int w = tid >> 5, lane = tid & 31;
                int l = pq * 16 + w;
                const float* ct = g_ctr + ((size_t)pb * LL + l) * AA;  // L1-resident
                float p = 0.f;
#pragma unroll
                for (int j = 0; j < 8; j++) {
                    int a = lane + j * 32;
                    p += tanh_ap(ct[a] + sAtt[a]) * sW2s[a];
                }
#pragma unroll
                for (int o = 16; o > 0; o >>= 1) p += __shfl_xor_sync(0xffffffffu, p, o);
                if (lane == 0)
                    g_e[l * 32 + pb] = __expf(p + b2v) * (float)cmask[pb * LL + l];
            }
            __syncthreads();
            if (tid == 0) st_release(&g_fe[bid * 32], gen);
            if (tid < 128) {
                while (ld_acquire(&g_fe[tid * 32]) < gen) { }
            }
            __syncthreads();
            // load all e [l][b]
            ((float4*)sE)[tid] = __ldcg(((const float4*)g_e) + tid);
            __syncthreads();
            if (tid < 32) {
                float s = 0.f;
#pragma unroll
                for (int i = 0; i < 64; i++) s += sE[i * 32 + tid];
                sSumA[tid] = __fdividef(1.0f, s);
            }
            __syncthreads();
            // a-pairs [l2][b] + scalar a for own batch
            {
                for (int i = tid; i < 1024; i += NTH) {
                    int l2 = i >> 5, b = i & 31;
                    float rs = sSumA[b];
                    sApr64[i] = pk2(sE[(2 * l2) * 32 + b] * rs,
                                    sE[(2 * l2 + 1) * 32 + b] * rs);
                }
                if (tid < 64) sA[tid] = sE[tid * 32 + pb] * sSumA[pb];
            }
            __syncthreads();
            // gsum from registers
            {
                int ci = tid >> 5, b = tid & 31;
                u64 acc = 0;
#pragma unroll
                for (int li = 0; li < 32; li++)
                    acc = fma2(rv[li], sApr64[li * 32 + b], acc);
                float2 r = upk2(acc);
                sDot[ci * 32 + b] = r.x + r.y;
            }
            __syncthreads();
            // ===== fused epilogue FIRST (h publication is the critical path) =====
            if (tid < 64) {
                int b = tid & 31, j = tid >> 5;
                float m = mask[b * TT + t];
                float hn2[2], cn2[2];
#pragma unroll
                for (int pp = 0; pp < 2; pp++) {
                    int chI = 2 * j + pp;
                    float gs[4];
#pragma unroll
                    for (int g = 0; g < 4; g++) {
                        int ci = g * 4 + chI;
                        gs[g] = sAcc[ci * 32 + b] + sDot[ci * 32 + b];
                    }
                    float cprev = sCst[chI * 32 + b];
                    float hprev = sHst[chI * 32 + b];
                    float iv = sig_ap(gs[0]);
                    float fv = sig_ap(gs[1]);
                    float gv = tanh_ap(gs[2]);
                    float ov = sig_ap(gs[3]);
                    float cn = fv * cprev + iv * gv;
                    float hn = ov * tanh_ap(cn);
                    hn = (1.f - m) * hprev + m * hn;
                    cn = (1.f - m) * cprev + m * cn;
                    sCst[chI * 32 + b] = cn;
                    sHst[chI * 32 + b] = hn;
                    hn2[pp] = hn; cn2[pp] = cn;
                }
                int ch = ch0 + 2 * j;
                *(u64*)&hwrite[((size_t)(ch >> 1) * 32 + b) * 2] = pk2(hn2[0], hn2[1]);
                *(float2*)(out_h + ((size_t)b * TT + t) * HH + ch) = make_float2(hn2[0], hn2[1]);
                *(float2*)(out_c + ((size_t)b * TT + t) * HH + ch) = make_float2(cn2[0], cn2[1]);
            }
            __syncthreads();
            if (tid == 0) st_release(&g_fh[bid * 32], gen);
            // ===== out_x (off the inter-block critical path) =====
            if (tid < 256) {
                int lg = tid >> 5, d4 = tid & 31;
                float4 xp = make_float4(0.f, 0.f, 0.f, 0.f);
                const float* cb = context + ((size_t)pb * LL + lg * 8) * DD + pq * 128 + d4 * 4;
#pragma unroll
                for (int li = 0; li < 8; li++) {
                    float av = sA[lg * 8 + li];
                    float4 v = *(const float4*)(cb + (size_t)li * DD);
                    xp.x += av * v.x; xp.y += av * v.y; xp.z += av * v.z; xp.w += av * v.w;
                }
                *(float4*)&sRed[tid * 4] = xp;
            }
            __syncthreads();
            if (tid < 32) {
                float4 s = make_float4(0.f, 0.f, 0.f, 0.f);
#pragma unroll
                for (int lg = 0; lg < 8; lg++) {
                    float4 v = *(const float4*)&sRed[(lg * 32 + tid) * 4];
                    s.x += v.x; s.y += v.y; s.z += v.z; s.w += v.w;
                }
                *(float4*)(out_x + ((size_t)pb * TT + t) * DD + pq * 128 + tid * 4) = s;
            }
            // ===== end-of-step barrier on col h-flags =====
            if (tid < 128) {
                while (ld_acquire(&g_fh[tid * 32]) < gen) { }
            }
            __syncthreads();
        }
    }

    if (bid == 0 && tid == 0)
        st_release(&g_epoch, base + (unsigned)TT);
}

// ---------------- host launcher: fork-join multi-stream prologue ----------------
extern "C" void kernel_launch(void* const* d_in, const int* in_sizes, int n_in,
                              void* d_out, int out_size) {
    (void)in_sizes; (void)n_in; (void)out_size;
    const float* X    = (const float*)d_in[0];
    const float* ctx  = (const float*)d_in[1];
    const float* mask = (const float*)d_in[2];
    const int*   cm   = (const int*)d_in[3];
    const float* W[4]; const float* U[4]; const float* C[4]; const float* bi[4];
    for (int gg = 0; gg < 4; gg++) {
        W[gg]  = (const float*)d_in[4 + 4 * gg];
        U[gg]  = (const float*)d_in[5 + 4 * gg];
        C[gg]  = (const float*)d_in[6 + 4 * gg];
        bi[gg] = (const float*)d_in[7 + 4 * gg];
    }
    const float* attW1c = (const float*)d_in[20];
    const float* attW1h = (const float*)d_in[21];
    const float* attB1  = (const float*)d_in[22];
    const float* attW2  = (const float*)d_in[23];
    const float* attB2  = (const float*)d_in[24];
    float* out = (float*)d_out;

    float *xg_ptr = nullptr, *ctr_ptr = nullptr, *ctxC_ptr = nullptr, *zb_ptr = nullptr;
    cudaGetSymbolAddress((void**)&xg_ptr, g_xg);
    cudaGetSymbolAddress((void**)&ctr_ptr, g_ctr);
    cudaGetSymbolAddress((void**)&ctxC_ptr, g_ctxC);
    cudaGetSymbolAddress((void**)&zb_ptr, g_zbias);

    size_t smem_bytes = (size_t)SMEM_FLOATS * sizeof(float);
    static cudaStream_t s2 = nullptr;
    static cudaEvent_t evF = nullptr, evJ = nullptr;
    static bool init_done = false;
    if (!init_done) {           // first call is the uncaptured correctness run
        cudaFuncSetAttribute(recur_kernel, cudaFuncAttributeMaxDynamicSharedMemorySize,
                             (int)smem_bytes);
        cudaStreamCreateWithFlags(&s2, cudaStreamNonBlocking);
        cudaEventCreateWithFlags(&evF, cudaEventDisableTiming);
        cudaEventCreateWithFlags(&evJ, cudaEventDisableTiming);
        init_done = true;
    }

    // fork: side stream runs the two context GEMMs in parallel with the big xg GEMM
    cudaEventRecord(evF, 0);
    cudaStreamWaitEvent(s2, evF, 0);
    dim3 grid2(AA / 64, (BB * LL) / 64);
    gemm_proj<<<grid2, 256, 0, s2>>>(ctx, attW1c, attW1c, attW1c, attW1c,
                                     attB1, attB1, attB1, attB1,
                                     ctr_ptr, AA, AA, AA, 0);
    dim3 grid3(NCOL / 64, (BB * LL) / 64);
    gemm_proj<<<grid3, 256, 0, s2>>>(ctx, C[0], C[1], C[2], C[3],
                                     zb_ptr, zb_ptr, zb_ptr, zb_ptr,
                                     ctxC_ptr, NCOL, 512, 512, 0);
    cudaEventRecord(evJ, s2);

    // main stream: xg = X@W + b : rows (t*32+b), cols 2048
    dim3 grid1(NCOL / 64, (TT * BB) / 64);
    gemm_proj<<<grid1, 256>>>(X, W[0], W[1], W[2], W[3],
                              bi[0], bi[1], bi[2], bi[3],
                              xg_ptr, NCOL, 512, 512, 1);

    // join, then the persistent recurrence
    cudaStreamWaitEvent(0, evJ, 0);
    recur_kernel<<<NBLK, NTH, smem_bytes>>>(ctx, mask, cm,
                                            U[0], U[1], U[2], U[3], attW1h,
                                            attW2, attB2, out);
}

// round 16
// speedup vs baseline: 1.6637x; 1.1305x over previous
#include <cuda_runtime.h>
#include <cstdint>
#include <cstddef>

#define BB 32
#define TT 128
#define LL 64
#define HH 512
#define AA 256
#define DD 512
#define NCOL 2048
#define NBLK 144
#define NTH 512

typedef unsigned long long u64;

// ---------------- device scratch ----------------
__device__ float g_xg[(size_t)TT * BB * NCOL];     // [t*32+b][col]
__device__ float g_ctr[(size_t)BB * LL * AA];      // ctx_trans [b*64+l][a]
__device__ float g_ctxC[(size_t)BB * LL * NCOL];   // context@C [b*64+l][col]
__device__ float g_attv[(size_t)BB * AA];          // [b][a]
__device__ float g_e[(size_t)LL * BB];             // raw exp scores [l*32+b]
__device__ float g_hpA[(size_t)256 * BB * 2];      // h pair buffers [k2][b]{e,o}
__device__ float g_hpB[(size_t)256 * BB * 2];
__device__ float g_zbias[512];
__device__ unsigned g_fatt[16 * 32];               // padded flags (128B apart)
__device__ unsigned g_fe[128 * 32];
__device__ unsigned g_fh[128 * 32];
__device__ unsigned g_epoch;

// ---------------- helpers ----------------
__device__ __forceinline__ u64 pk2(float lo, float hi) {
    u64 r; asm("mov.b64 %0, {%1,%2};" : "=l"(r) : "f"(lo), "f"(hi)); return r;
}
__device__ __forceinline__ float2 upk2(u64 v) {
    float2 r; asm("mov.b64 {%0,%1}, %2;" : "=f"(r.x), "=f"(r.y) : "l"(v)); return r;
}
__device__ __forceinline__ u64 fma2(u64 a, u64 b, u64 c) {
    u64 d; asm("fma.rn.f32x2 %0, %1, %2, %3;" : "=l"(d) : "l"(a), "l"(b), "l"(c)); return d;
}
__device__ __forceinline__ float tanh_ap(float x) {
    float y; asm("tanh.approx.f32 %0, %1;" : "=f"(y) : "f"(x)); return y;
}
__device__ __forceinline__ float sig_ap(float x) {
    return fmaf(tanh_ap(0.5f * x), 0.5f, 0.5f);
}
__device__ __forceinline__ void st_release(unsigned* p, unsigned v) {
    asm volatile("st.release.gpu.global.u32 [%0], %1;" :: "l"(p), "r"(v) : "memory");
}
__device__ __forceinline__ unsigned ld_acquire(const unsigned* p) {
    unsigned v;
    asm volatile("ld.acquire.gpu.global.u32 %0, [%1];" : "=r"(v) : "l"(p) : "memory");
    return v;
}

// ---------------- prologue GEMM v2: 64x128 tile, 8m x 4n pairs per thread ----------------
__global__ void __launch_bounds__(256) gemm_proj2(
    const float* __restrict__ A,
    const float* __restrict__ Wa, const float* __restrict__ Wb,
    const float* __restrict__ Wc, const float* __restrict__ Wd,
    const float* __restrict__ ba, const float* __restrict__ bbi,
    const float* __restrict__ bc, const float* __restrict__ bd,
    float* __restrict__ Out, int Ncols, int wN, int wstride, int tb_mode)
{
    __shared__ u64 As2[2][8][64];    // [buf][k2][m]
    __shared__ u64 Bs2[2][8][128];   // [buf][k2][n]
    int tid = threadIdx.x;
    int ntile = blockIdx.x, mtile = blockIdx.y;

    int gate = (ntile * 128) / 512;
    const float* Wsel = (gate == 0) ? Wa : (gate == 1) ? Wb : (gate == 2) ? Wc : Wd;
    const float* bsel = (gate == 0) ? ba : (gate == 1) ? bbi : (gate == 2) ? bc : bd;
    int ncolbase = (ntile * 128) % wN;

    // A loader: 64 rows x 16 k, float4 along k
    int a_r = tid >> 2;
    int a_k = (tid & 3) * 4;
    int grow = mtile * 64 + a_r;
    const float* aptr;
    if (tb_mode) {
        int t = grow >> 5, b = grow & 31;
        aptr = A + ((size_t)(b * TT + t)) * DD;
    } else {
        aptr = A + (size_t)grow * DD;
    }
    // B loader: all 256 threads; 8 k2-rows x 128 n, 4 n-cols per thread
    int bl_k2 = tid >> 5;
    int bl_n  = (tid & 31) * 4;

    // compute roles: 8m x 4n per thread
    int tx = tid & 31;     // n block: cols tx*4 .. tx*4+3
    int ty = tid >> 5;     // m block: rows ty*8 .. ty*8+7 (warp-uniform -> A broadcast)

    u64 acc2[8][4];
#pragma unroll
    for (int i = 0; i < 8; i++)
#pragma unroll
        for (int j = 0; j < 4; j++) acc2[i][j] = 0;

    // preload k-chunk 0
    float4 av = *(const float4*)(aptr + a_k);
    float4 b0 = *(const float4*)(Wsel + (size_t)(2 * bl_k2) * wstride + ncolbase + bl_n);
    float4 b1 = *(const float4*)(Wsel + (size_t)(2 * bl_k2 + 1) * wstride + ncolbase + bl_n);
    As2[0][(a_k >> 1)][a_r]     = pk2(av.x, av.y);
    As2[0][(a_k >> 1) + 1][a_r] = pk2(av.z, av.w);
    Bs2[0][bl_k2][bl_n + 0] = pk2(b0.x, b1.x);
    Bs2[0][bl_k2][bl_n + 1] = pk2(b0.y, b1.y);
    Bs2[0][bl_k2][bl_n + 2] = pk2(b0.z, b1.z);
    Bs2[0][bl_k2][bl_n + 3] = pk2(b0.w, b1.w);
    __syncthreads();

    const int NIT = DD / 16;   // 32
    for (int it = 0; it < NIT; it++) {
        int buf = it & 1;
        float4 av_n, b0_n, b1_n;
        if (it + 1 < NIT) {
            int k0 = (it + 1) * 16;
            av_n = *(const float4*)(aptr + k0 + a_k);
            b0_n = *(const float4*)(Wsel + (size_t)(k0 + 2 * bl_k2) * wstride + ncolbase + bl_n);
            b1_n = *(const float4*)(Wsel + (size_t)(k0 + 2 * bl_k2 + 1) * wstride + ncolbase + bl_n);
        }
#pragma unroll
        for (int k2 = 0; k2 < 8; k2++) {
            ulonglong2 a01 = *(const ulonglong2*)&As2[buf][k2][ty * 8];
            ulonglong2 a23 = *(const ulonglong2*)&As2[buf][k2][ty * 8 + 2];
            ulonglong2 a45 = *(const ulonglong2*)&As2[buf][k2][ty * 8 + 4];
            ulonglong2 a67 = *(const ulonglong2*)&As2[buf][k2][ty * 8 + 6];
            ulonglong2 b01 = *(const ulonglong2*)&Bs2[buf][k2][tx * 4];
            ulonglong2 b23 = *(const ulonglong2*)&Bs2[buf][k2][tx * 4 + 2];
            u64 aa[8] = {a01.x, a01.y, a23.x, a23.y, a45.x, a45.y, a67.x, a67.y};
            u64 bb4[4] = {b01.x, b01.y, b23.x, b23.y};
#pragma unroll
            for (int i = 0; i < 8; i++)
#pragma unroll
                for (int j = 0; j < 4; j++) acc2[i][j] = fma2(aa[i], bb4[j], acc2[i][j]);
        }
        if (it + 1 < NIT) {
            int nb = (it + 1) & 1;
            __syncthreads();
            As2[nb][(a_k >> 1)][a_r]     = pk2(av_n.x, av_n.y);
            As2[nb][(a_k >> 1) + 1][a_r] = pk2(av_n.z, av_n.w);
            Bs2[nb][bl_k2][bl_n + 0] = pk2(b0_n.x, b1_n.x);
            Bs2[nb][bl_k2][bl_n + 1] = pk2(b0_n.y, b1_n.y);
            Bs2[nb][bl_k2][bl_n + 2] = pk2(b0_n.z, b1_n.z);
            Bs2[nb][bl_k2][bl_n + 3] = pk2(b0_n.w, b1_n.w);
            __syncthreads();
        }
    }
#pragma unroll
    for (int i = 0; i < 8; i++) {
        int gr = mtile * 64 + ty * 8 + i;
        float r[4];
#pragma unroll
        for (int j = 0; j < 4; j++) {
            float2 v = upk2(acc2[i][j]);
            r[j] = v.x + v.y + bsel[ncolbase + tx * 4 + j];
        }
        *(float4*)(Out + (size_t)gr * Ncols + ntile * 128 + tx * 4) =
            make_float4(r[0], r[1], r[2], r[3]);
    }
}

// smem map (floats)
#define OFF_H    8192
#define OFF_RED  24576
#define OFF_ACC  28672
#define OFF_DOT  29184
#define OFF_E    29696
#define OFF_APR  31744
#define OFF_ATT  33792
#define OFF_A    34048
#define OFF_W2   34112
#define OFF_SUMA 34368
#define OFF_CST  34400
#define OFF_HST  34528
#define SMEM_FLOATS 34656

// ---------------- persistent recurrent kernel (R12/R15 structure, unchanged) ----------------
__global__ void __launch_bounds__(NTH, 1) recur_kernel(
    const float* __restrict__ context,
    const float* __restrict__ mask,
    const int*   __restrict__ cmask,
    const float* __restrict__ U0, const float* __restrict__ U1,
    const float* __restrict__ U2, const float* __restrict__ U3,
    const float* __restrict__ W1h,
    const float* __restrict__ W2, const float* __restrict__ b2,
    float* __restrict__ out)
{
    extern __shared__ float smem[];
    u64*   sW64   = (u64*)smem;                    // [k2][16 cols] pairs
    float* sH     = smem + OFF_H;                  // h pairs [k2][32 b]
    u64*   sH64   = (u64*)sH;
    float* sRed   = smem + OFF_RED;                // 4096
    float* sAcc   = smem + OFF_ACC;                // 512 [ci][b]
    float* sDot   = smem + OFF_DOT;                // 512 [ci][b]
    float* sE     = smem + OFF_E;                  // 2048 [l][b]
    u64*   sApr64 = (u64*)(smem + OFF_APR);        // 1024 [l2][b]
    float* sAtt   = smem + OFF_ATT;                // 256
    float* sA     = smem + OFF_A;                  // 64
    float* sW2s   = smem + OFF_W2;                 // 256
    float* sSumA  = smem + OFF_SUMA;               // 32
    float* sCst   = smem + OFF_CST;                // 128
    float* sHst   = smem + OFF_HST;                // 128

    const int tid = threadIdx.x;
    const int bid = blockIdx.x;
    const bool isCol = (bid < 128);
    float* out_h = out;
    float* out_c = out + (size_t)BB * TT * HH;
    float* out_x = out + (size_t)2 * BB * TT * HH;
    const float b2v = b2[0];

    unsigned base = ld_acquire(&g_epoch);

    // roles
    const int ch0 = bid * 4;
    const int ab  = bid - 128;
    const int pb  = bid >> 2;
    const int pq  = bid & 3;

    // P1 thread roles: 2 cols x 4 b x 32 k2
    const int cp = tid & 7;
    const int bq = (tid >> 3) & 7;
    const int kq = tid >> 6;

    // ---- startup: weight slice into SMEM ----
    for (int i = tid; i < 4096; i += NTH) {
        int k2 = i >> 4, ci = i & 15;
        float e, o;
        if (isCol) {
            int g = ci >> 2, ch = ch0 + (ci & 3);
            const float* Ug = (g == 0) ? U0 : (g == 1) ? U1 : (g == 2) ? U2 : U3;
            e = Ug[(size_t)(2 * k2) * 512 + ch];
            o = Ug[(size_t)(2 * k2 + 1) * 512 + ch];
        } else {
            int a = ab * 16 + ci;
            e = W1h[(size_t)(2 * k2) * AA + a];
            o = W1h[(size_t)(2 * k2 + 1) * AA + a];
        }
        sW64[i] = pk2(e, o);
    }
    // ---- startup: register-resident ctxC (col only) ----
    u64 rv[32];
    {
        int ci = tid >> 5, b = tid & 31;
        if (isCol) {
            int col = (ci >> 2) * 512 + ch0 + (ci & 3);
            const float* cc = g_ctxC + (size_t)(b * 64) * NCOL + col;
#pragma unroll
            for (int li = 0; li < 32; li++) {
                float e = cc[(size_t)(2 * li) * NCOL];
                float o = cc[(size_t)(2 * li + 1) * NCOL];
                rv[li] = pk2(e, o);
            }
        } else {
#pragma unroll
            for (int li = 0; li < 32; li++) rv[li] = 0;
        }
    }
    if (tid < AA) sW2s[tid] = W2[tid];
    if (tid < 128) { sCst[tid] = 0.f; sHst[tid] = 0.f; }
    __syncthreads();

    for (int t = 0; t < TT; t++) {
        const unsigned gen = base + (unsigned)(t + 1);
        const float* hread = (t & 1) ? g_hpA : g_hpB;
        float* hwrite = (t & 1) ? g_hpB : g_hpA;

        // ===== prefetch xg early (hides L2 latency behind P1) =====
        float xgpre = 0.f;
        if (isCol) {
            int b = tid >> 4, ci = tid & 15;
            int col = (ci >> 2) * 512 + ch0 + (ci & 3);
            xgpre = __ldcg(&g_xg[((size_t)t * BB + b) * NCOL + col]);
        }

        // ===== load h broadcast (L2-direct) =====
        if (t > 0) {
            const float4* src = (const float4*)hread;
            float4* dst = (float4*)sH;
            for (int f4 = tid; f4 < 4096; f4 += NTH) dst[f4] = __ldcg(src + f4);
        }
        __syncthreads();

        // ===== P1 matvec: 2 cols x 4 b per thread =====
        u64 ac[2][4];
#pragma unroll
        for (int i = 0; i < 2; i++)
#pragma unroll
            for (int j = 0; j < 4; j++) ac[i][j] = 0;
        if (t > 0) {
            const u64* wp = sW64 + (kq * 32) * 16 + cp * 2;
            const u64* hp = sH64 + (kq * 32) * 32 + bq * 4;
#pragma unroll 8
            for (int p = 0; p < 32; p++) {
                ulonglong2 w2 = *(const ulonglong2*)wp;
                ulonglong2 ha = *(const ulonglong2*)hp;
                ulonglong2 hb = *(const ulonglong2*)(hp + 2);
                ac[0][0] = fma2(w2.x, ha.x, ac[0][0]);
                ac[0][1] = fma2(w2.x, ha.y, ac[0][1]);
                ac[0][2] = fma2(w2.x, hb.x, ac[0][2]);
                ac[0][3] = fma2(w2.x, hb.y, ac[0][3]);
                ac[1][0] = fma2(w2.y, ha.x, ac[1][0]);
                ac[1][1] = fma2(w2.y, ha.y, ac[1][1]);
                ac[1][2] = fma2(w2.y, hb.x, ac[1][2]);
                ac[1][3] = fma2(w2.y, hb.y, ac[1][3]);
                wp += 16; hp += 32;
            }
        }
#pragma unroll
        for (int bi = 0; bi < 4; bi++) {
            float2 r0 = upk2(ac[0][bi]);
            float2 r1 = upk2(ac[1][bi]);
            *(float2*)&sRed[kq * 512 + (bq * 4 + bi) * 16 + cp * 2] =
                make_float2(r0.x + r0.y, r1.x + r1.y);
        }
        __syncthreads();
        {
            float s = 0.f;
#pragma unroll
            for (int q = 0; q < 8; q++) s += sRed[q * 512 + tid];
            int b = tid >> 4, ci = tid & 15;
            if (isCol) {
                sAcc[ci * 32 + b] = s + xgpre;
            } else {
                g_attv[b * AA + ab * 16 + ci] = s;
            }
        }
        __syncthreads();

        if (!isCol) {
            // att block: publish attv, then wait out the step
            if (tid == 0) st_release(&g_fatt[ab * 32], gen);
            if (tid < 128) {
                while (ld_acquire(&g_fh[tid * 32]) < gen) { }
            }
            __syncthreads();
        } else {
            // ===== col: wait attv, distributed scores =====
            if (tid < 16) {
                while (ld_acquire(&g_fatt[tid * 32]) < gen) { }
            }
            __syncthreads();
            if (tid < AA) sAtt[tid] = __ldcg(&g_attv[pb * AA + tid]);
            __syncthreads();
            {
                int w = tid >> 5, lane = tid & 31;
                int l = pq * 16 + w;
                const float* ct = g_ctr + ((size_t)pb * LL + l) * AA;  // L1-resident
                float p = 0.f;
#pragma unroll
                for (int j = 0; j < 8; j++) {
                    int a = lane + j * 32;
                    p += tanh_ap(ct[a] + sAtt[a]) * sW2s[a];
                }
#pragma unroll
                for (int o = 16; o > 0; o >>= 1) p += __shfl_xor_sync(0xffffffffu, p, o);
                if (lane == 0)
                    g_e[l * 32 + pb] = __expf(p + b2v) * (float)cmask[pb * LL + l];
            }
            __syncthreads();
            if (tid == 0) st_release(&g_fe[bid * 32], gen);
            if (tid < 128) {
                while (ld_acquire(&g_fe[tid * 32]) < gen) { }
            }
            __syncthreads();
            // load all e [l][b]
            ((float4*)sE)[tid] = __ldcg(((const float4*)g_e) + tid);
            __syncthreads();
            if (tid < 32) {
                float s = 0.f;
#pragma unroll
                for (int i = 0; i < 64; i++) s += sE[i * 32 + tid];
                sSumA[tid] = __fdividef(1.0f, s);
            }
            __syncthreads();
            // a-pairs [l2][b] + scalar a for own batch
            {
                for (int i = tid; i < 1024; i += NTH) {
                    int l2 = i >> 5, b = i & 31;
                    float rs = sSumA[b];
                    sApr64[i] = pk2(sE[(2 * l2) * 32 + b] * rs,
                                    sE[(2 * l2 + 1) * 32 + b] * rs);
                }
                if (tid < 64) sA[tid] = sE[tid * 32 + pb] * sSumA[pb];
            }
            __syncthreads();
            // gsum from registers
            {
                int ci = tid >> 5, b = tid & 31;
                u64 acc = 0;
#pragma unroll
                for (int li = 0; li < 32; li++)
                    acc = fma2(rv[li], sApr64[li * 32 + b], acc);
                float2 r = upk2(acc);
                sDot[ci * 32 + b] = r.x + r.y;
            }
            __syncthreads();
            // ===== fused epilogue FIRST (h publication is the critical path) =====
            if (tid < 64) {
                int b = tid & 31, j = tid >> 5;
                float m = mask[b * TT + t];
                float hn2[2], cn2[2];
#pragma unroll
                for (int pp = 0; pp < 2; pp++) {
                    int chI = 2 * j + pp;
                    float gs[4];
#pragma unroll
                    for (int g = 0; g < 4; g++) {
                        int ci = g * 4 + chI;
                        gs[g] = sAcc[ci * 32 + b] + sDot[ci * 32 + b];
                    }
                    float cprev = sCst[chI * 32 + b];
                    float hprev = sHst[chI * 32 + b];
                    float iv = sig_ap(gs[0]);
                    float fv = sig_ap(gs[1]);
                    float gv = tanh_ap(gs[2]);
                    float ov = sig_ap(gs[3]);
                    float cn = fv * cprev + iv * gv;
                    float hn = ov * tanh_ap(cn);
                    hn = (1.f - m) * hprev + m * hn;
                    cn = (1.f - m) * cprev + m * cn;
                    sCst[chI * 32 + b] = cn;
                    sHst[chI * 32 + b] = hn;
                    hn2[pp] = hn; cn2[pp] = cn;
                }
                int ch = ch0 + 2 * j;
                *(u64*)&hwrite[((size_t)(ch >> 1) * 32 + b) * 2] = pk2(hn2[0], hn2[1]);
                *(float2*)(out_h + ((size_t)b * TT + t) * HH + ch) = make_float2(hn2[0], hn2[1]);
                *(float2*)(out_c + ((size_t)b * TT + t) * HH + ch) = make_float2(cn2[0], cn2[1]);
            }
            __syncthreads();
            if (tid == 0) st_release(&g_fh[bid * 32], gen);
            // ===== out_x (off the inter-block critical path) =====
            if (tid < 256) {
                int lg = tid >> 5, d4 = tid & 31;
                float4 xp = make_float4(0.f, 0.f, 0.f, 0.f);
                const float* cb = context + ((size_t)pb * LL + lg * 8) * DD + pq * 128 + d4 * 4;
#pragma unroll
                for (int li = 0; li < 8; li++) {
                    float av = sA[lg * 8 + li];
                    float4 v = *(const float4*)(cb + (size_t)li * DD);
                    xp.x += av * v.x; xp.y += av * v.y; xp.z += av * v.z; xp.w += av * v.w;
                }
                *(float4*)&sRed[tid * 4] = xp;
            }
            __syncthreads();
            if (tid < 32) {
                float4 s = make_float4(0.f, 0.f, 0.f, 0.f);
#pragma unroll
                for (int lg = 0; lg < 8; lg++) {
                    float4 v = *(const float4*)&sRed[(lg * 32 + tid) * 4];
                    s.x += v.x; s.y += v.y; s.z += v.z; s.w += v.w;
                }
                *(float4*)(out_x + ((size_t)pb * TT + t) * DD + pq * 128 + tid * 4) = s;
            }
            // ===== end-of-step barrier on col h-flags =====
            if (tid < 128) {
                while (ld_acquire(&g_fh[tid * 32]) < gen) { }
            }
            __syncthreads();
        }
    }

    if (bid == 0 && tid == 0)
        st_release(&g_epoch, base + (unsigned)TT);
}

// ---------------- host launcher: fork-join multi-stream prologue ----------------
extern "C" void kernel_launch(void* const* d_in, const int* in_sizes, int n_in,
                              void* d_out, int out_size) {
    (void)in_sizes; (void)n_in; (void)out_size;
    const float* X    = (const float*)d_in[0];
    const float* ctx  = (const float*)d_in[1];
    const float* mask = (const float*)d_in[2];
    const int*   cm   = (const int*)d_in[3];
    const float* W[4]; const float* U[4]; const float* C[4]; const float* bi[4];
    for (int gg = 0; gg < 4; gg++) {
        W[gg]  = (const float*)d_in[4 + 4 * gg];
        U[gg]  = (const float*)d_in[5 + 4 * gg];
        C[gg]  = (const float*)d_in[6 + 4 * gg];
        bi[gg] = (const float*)d_in[7 + 4 * gg];
    }
    const float* attW1c = (const float*)d_in[20];
    const float* attW1h = (const float*)d_in[21];
    const float* attB1  = (const float*)d_in[22];
    const float* attW2  = (const float*)d_in[23];
    const float* attB2  = (const float*)d_in[24];
    float* out = (float*)d_out;

    float *xg_ptr = nullptr, *ctr_ptr = nullptr, *ctxC_ptr = nullptr, *zb_ptr = nullptr;
    cudaGetSymbolAddress((void**)&xg_ptr, g_xg);
    cudaGetSymbolAddress((void**)&ctr_ptr, g_ctr);
    cudaGetSymbolAddress((void**)&ctxC_ptr, g_ctxC);
    cudaGetSymbolAddress((void**)&zb_ptr, g_zbias);

    size_t smem_bytes = (size_t)SMEM_FLOATS * sizeof(float);
    static cudaStream_t s2 = nullptr;
    static cudaEvent_t evF = nullptr, evJ = nullptr;
    static bool init_done = false;
    if (!init_done) {           // first call is the uncaptured correctness run
        cudaFuncSetAttribute(recur_kernel, cudaFuncAttributeMaxDynamicSharedMemorySize,
                             (int)smem_bytes);
        cudaStreamCreateWithFlags(&s2, cudaStreamNonBlocking);
        cudaEventCreateWithFlags(&evF, cudaEventDisableTiming);
        cudaEventCreateWithFlags(&evJ, cudaEventDisableTiming);
        init_done = true;
    }

    // fork: side stream runs the two context GEMMs in parallel with the big xg GEMM
    cudaEventRecord(evF, 0);
    cudaStreamWaitEvent(s2, evF, 0);
    dim3 grid2(AA / 128, (BB * LL) / 64);
    gemm_proj2<<<grid2, 256, 0, s2>>>(ctx, attW1c, attW1c, attW1c, attW1c,
                                      attB1, attB1, attB1, attB1,
                                      ctr_ptr, AA, AA, AA, 0);
    dim3 grid3(NCOL / 128, (BB * LL) / 64);
    gemm_proj2<<<grid3, 256, 0, s2>>>(ctx, C[0], C[1], C[2], C[3],
                                      zb_ptr, zb_ptr, zb_ptr, zb_ptr,
                                      ctxC_ptr, NCOL, 512, 512, 0);
    cudaEventRecord(evJ, s2);

    // main stream: xg = X@W + b : rows (t*32+b), cols 2048
    dim3 grid1(NCOL / 128, (TT * BB) / 64);
    gemm_proj2<<<grid1, 256>>>(X, W[0], W[1], W[2], W[3],
                               bi[0], bi[1], bi[2], bi[3],
                               xg_ptr, NCOL, 512, 512, 1);

    // join, then the persistent recurrence
    cudaStreamWaitEvent(0, evJ, 0);
    recur_kernel<<<NBLK, NTH, smem_bytes>>>(ctx, mask, cm,
                                            U[0], U[1], U[2], U[3], attW1h,
                                            attW2, attB2, out);
}